// round 7
// baseline (speedup 1.0000x reference)
#include <cuda_runtime.h>
#include <cstdint>

#define D_DIM   2048
#define NROWS   16          // 8 group rows (W1) + 8 expert rows (W2)
#define TOKENS  32768       // 4 * 8192
#define T_TOK   4           // tokens per thread (W register-reuse factor)
#define NTILES  (TOKENS / T_TOK)   // 8192 warp-tiles
#define BLOCK   256
#define GRID    152
#define SMEM_BYTES (NROWS * D_DIM * 4)   // 131072

__device__ __forceinline__ void ffma2(unsigned long long &acc,
                                      unsigned long long a,
                                      unsigned long long b) {
    asm("fma.rn.f32x2 %0, %1, %2, %0;" : "+l"(acc) : "l"(a), "l"(b));
}

extern "C" __global__ void __launch_bounds__(BLOCK, 1)
router_kernel(const float* __restrict__ x,
              const float* __restrict__ W1,
              const float* __restrict__ W2,
              float* __restrict__ out)
{
    extern __shared__ float Wsh[];   // [NROWS][D_DIM], rows 0..7 = W1, 8..15 = W2

    // Cooperative load of all 16 weight rows into shared (L2-resident source).
    {
        int tid = threadIdx.x;
        for (int idx = tid * 4; idx < 8 * D_DIM; idx += BLOCK * 4) {
            *reinterpret_cast<float4*>(Wsh + idx) =
                *reinterpret_cast<const float4*>(W1 + idx);
            *reinterpret_cast<float4*>(Wsh + 8 * D_DIM + idx) =
                *reinterpret_cast<const float4*>(W2 + idx);
        }
        __syncthreads();
    }

    const int lane   = threadIdx.x & 31;
    const int warp   = blockIdx.x * (BLOCK / 32) + (threadIdx.x >> 5);
    const int nwarps = GRID * (BLOCK / 32);

    for (int tile = warp; tile < NTILES; tile += nwarps) {
        const int tok0 = tile * T_TOK;
        const float* xb = x + (size_t)tok0 * D_DIM;

        // Packed f32x2 accumulators: 16 rows x 4 tokens (each holds 2 partial sums)
        unsigned long long acc[NROWS][T_TOK];
        #pragma unroll
        for (int r = 0; r < NROWS; r++)
            #pragma unroll
            for (int t = 0; t < T_TOK; t++)
                acc[r][t] = 0ull;

        // Lane ll owns d-elements {128*i + 4*ll .. +3} for i = 0..15.
        // x loads: 512B contiguous per warp instruction (perfect coalescing).
        // W loads: LDS.128, 16B stride across lanes (conflict-free).
        #pragma unroll 2
        for (int i = 0; i < 16; i++) {
            const int off = i * 128 + lane * 4;
            ulonglong2 xv[T_TOK];
            #pragma unroll
            for (int t = 0; t < T_TOK; t++)
                xv[t] = *reinterpret_cast<const ulonglong2*>(xb + t * D_DIM + off);
            #pragma unroll
            for (int r = 0; r < NROWS; r++) {
                ulonglong2 wv = *reinterpret_cast<const ulonglong2*>(Wsh + r * D_DIM + off);
                #pragma unroll
                for (int t = 0; t < T_TOK; t++) {
                    ffma2(acc[r][t], xv[t].x, wv.x);
                    ffma2(acc[r][t], xv[t].y, wv.y);
                }
            }
        }

        // Cross-lane reduction: fold packed halves, butterfly-allreduce each
        // (row, token) scalar; lane t keeps the 16 sums for token t in regs
        // (static indices only -> no local-memory spill).
        float gs[8], es[8];
        #pragma unroll
        for (int r = 0; r < NROWS; r++) {
            #pragma unroll
            for (int t = 0; t < T_TOK; t++) {
                float2 f = *reinterpret_cast<float2*>(&acc[r][t]);
                float v = f.x + f.y;
                #pragma unroll
                for (int o = 16; o > 0; o >>= 1)
                    v += __shfl_xor_sync(0xffffffffu, v, o);
                if (lane == t) {
                    if (r < 8) gs[r] = v;
                    else       es[r - 8] = v;
                }
            }
        }

        // Epilogue: lanes 0..3 each finish one token.
        if (lane < T_TOK) {
            const int tok = tok0 + lane;

            // top-2 of 8 with lax.top_k tie rule (lowest index wins):
            // strict '>' on an ascending scan keeps the earliest max.
            float g1v = gs[0]; int g1 = 0;
            #pragma unroll
            for (int k = 1; k < 8; k++) if (gs[k] > g1v) { g1v = gs[k]; g1 = k; }
            float g2v = -3.402823466e+38f; int g2 = 0;
            #pragma unroll
            for (int k = 0; k < 8; k++) if (k != g1 && gs[k] > g2v) { g2v = gs[k]; g2 = k; }

            float e1v = es[0]; int e1 = 0;
            #pragma unroll
            for (int k = 1; k < 8; k++) if (es[k] > e1v) { e1v = es[k]; e1 = k; }
            float e2v = -3.402823466e+38f; int e2 = 0;
            #pragma unroll
            for (int k = 0; k < 8; k++) if (k != e1 && es[k] > e2v) { e2v = es[k]; e2 = k; }

            // combined scores in reference order: (g1,e1),(g1,e2),(g2,e1),(g2,e2)
            const float c0 = g1v + e1v;
            const float c1 = g1v + e2v;
            const float c2 = g2v + e1v;
            const float c3 = g2v + e2v;
            const float m  = fmaxf(fmaxf(c0, c1), fmaxf(c2, c3));
            float w0 = __expf(c0 - m);
            float w1 = __expf(c1 - m);
            float w2 = __expf(c2 - m);
            float w3 = __expf(c3 - m);
            const float inv = 1.0f / (w0 + w1 + w2 + w3);
            w0 *= inv; w1 *= inv; w2 *= inv; w3 *= inv;

            float4 idxv = make_float4((float)(g1 * 8 + e1), (float)(g1 * 8 + e2),
                                      (float)(g2 * 8 + e1), (float)(g2 * 8 + e2));
            float4 wv4  = make_float4(w0, w1, w2, w3);

            *reinterpret_cast<float4*>(out + (size_t)tok * 4) = idxv;
            *reinterpret_cast<float4*>(out + (size_t)TOKENS * 4 + (size_t)tok * 4) = wv4;
        }
    }
}

extern "C" void kernel_launch(void* const* d_in, const int* in_sizes, int n_in,
                              void* d_out, int out_size) {
    const float* x  = (const float*)d_in[0];
    const float* W1 = (const float*)d_in[1];
    const float* W2 = (const float*)d_in[2];
    float* out = (float*)d_out;

    cudaFuncSetAttribute(router_kernel,
                         cudaFuncAttributeMaxDynamicSharedMemorySize, SMEM_BYTES);
    router_kernel<<<GRID, BLOCK, SMEM_BYTES>>>(x, W1, W2, out);
}

// round 8
// speedup vs baseline: 1.1605x; 1.1605x over previous
#include <cuda_runtime.h>
#include <cstdint>

#define D_DIM   2048
#define NROWS   16          // 8 group rows (W1) + 8 expert rows (W2)
#define TOKENS  32768       // 4 * 8192
#define T_TOK   4           // tokens per thread tile
#define NTILES  (TOKENS / T_TOK)   // 8192 warp-tiles
#define BLOCK   256
#define GRID    152
#define SMEM_BYTES (NROWS * D_DIM * 4)   // 131072

__device__ __forceinline__ void ffma2(unsigned long long &acc,
                                      unsigned long long a,
                                      unsigned long long b) {
    asm("fma.rn.f32x2 %0, %1, %2, %0;" : "+l"(acc) : "l"(a), "l"(b));
}

// Load one 128-float block (4 tokens) into a register buffer.
#define LOADX(buf, xp, blk)                                                    \
    {                                                                          \
        _Pragma("unroll")                                                      \
        for (int t = 0; t < T_TOK; t++)                                        \
            buf[t] = *reinterpret_cast<const ulonglong2*>(                     \
                (xp) + (size_t)t * D_DIM + (blk) * 128);                       \
    }

// FMA one block: 16 rows x 4 tokens against W slice at wp (+blkoff floats).
#define COMPUTE(buf, wp, blkoff)                                               \
    {                                                                          \
        _Pragma("unroll")                                                      \
        for (int r = 0; r < NROWS; r++) {                                      \
            ulonglong2 wv = *reinterpret_cast<const ulonglong2*>(              \
                (wp) + r * D_DIM + (blkoff));                                  \
            _Pragma("unroll")                                                  \
            for (int t = 0; t < T_TOK; t++) {                                  \
                ffma2(acc[r][t], buf[t].x, wv.x);                              \
                ffma2(acc[r][t], buf[t].y, wv.y);                              \
            }                                                                  \
        }                                                                      \
    }

extern "C" __global__ void __launch_bounds__(BLOCK, 1)
router_kernel(const float* __restrict__ x,
              const float* __restrict__ W1,
              const float* __restrict__ W2,
              float* __restrict__ out)
{
    extern __shared__ float Wsh[];   // [NROWS][D_DIM], rows 0..7 = W1, 8..15 = W2

    {
        int tid = threadIdx.x;
        for (int idx = tid * 4; idx < 8 * D_DIM; idx += BLOCK * 4) {
            *reinterpret_cast<float4*>(Wsh + idx) =
                *reinterpret_cast<const float4*>(W1 + idx);
            *reinterpret_cast<float4*>(Wsh + 8 * D_DIM + idx) =
                *reinterpret_cast<const float4*>(W2 + idx);
        }
        __syncthreads();
    }

    const int lane   = threadIdx.x & 31;
    const int warp   = blockIdx.x * (BLOCK / 32) + (threadIdx.x >> 5);
    const int nwarps = GRID * (BLOCK / 32);

    const float* wp = Wsh + lane * 4;   // this lane's W base (16B-aligned)

    for (int tile = warp; tile < NTILES; tile += nwarps) {
        const int tok0 = tile * T_TOK;
        const float* xp = x + (size_t)tok0 * D_DIM + lane * 4;

        unsigned long long acc[NROWS][T_TOK];
        #pragma unroll
        for (int r = 0; r < NROWS; r++)
            #pragma unroll
            for (int t = 0; t < T_TOK; t++)
                acc[r][t] = 0ull;

        // 4-deep x prefetch pipeline: blocks of 128 floats, lane ll owns
        // d in {128*i + 4*ll .. +3}. 16 LDG.128 in flight per warp at start.
        ulonglong2 b0[T_TOK], b1[T_TOK], b2[T_TOK], b3[T_TOK];
        LOADX(b0, xp, 0);
        LOADX(b1, xp, 1);
        LOADX(b2, xp, 2);
        LOADX(b3, xp, 3);

        const float* wq = wp;
        const float* xq = xp;
        #pragma unroll 1
        for (int i = 0; i < 16; i += 4) {
            COMPUTE(b0, wq, 0);
            if (i < 12) LOADX(b0, xq, 4);
            COMPUTE(b1, wq, 128);
            if (i < 12) LOADX(b1, xq, 5);
            COMPUTE(b2, wq, 256);
            if (i < 12) LOADX(b2, xq, 6);
            COMPUTE(b3, wq, 384);
            if (i < 12) LOADX(b3, xq, 7);
            wq += 512;
            xq += 512;
        }

        // Pairwise split-lane reduction: reduce (group row r, expert row r+8)
        // together — 6 shfl per pair. Lanes 0-15 end with the group sum,
        // lanes 16-31 with the expert sum.
        float gs[8], es[8];
        #pragma unroll
        for (int r = 0; r < 8; r++) {
            #pragma unroll
            for (int t = 0; t < T_TOK; t++) {
                float2 fa = *reinterpret_cast<float2*>(&acc[r][t]);
                float2 fb = *reinterpret_cast<float2*>(&acc[r + 8][t]);
                float a = fa.x + fa.y;
                float b = fb.x + fb.y;
                float ta = __shfl_xor_sync(0xffffffffu, a, 16);
                float tb = __shfl_xor_sync(0xffffffffu, b, 16);
                float v = (lane & 16) ? (b + tb) : (a + ta);
                v += __shfl_xor_sync(0xffffffffu, v, 8);
                v += __shfl_xor_sync(0xffffffffu, v, 4);
                v += __shfl_xor_sync(0xffffffffu, v, 2);
                v += __shfl_xor_sync(0xffffffffu, v, 1);
                if (lane == t)      gs[r] = v;
                if (lane == 16 + t) es[r] = v;
            }
        }

        // Split epilogue: lane t does the group top-2, lane 16+t the expert
        // top-2 (all lanes run the scan; only those lanes hold valid data).
        float sv[8];
        #pragma unroll
        for (int k = 0; k < 8; k++)
            sv[k] = (lane < 16) ? gs[k] : es[k];

        // top-2 of 8, lax.top_k tie rule (lowest index wins).
        float b1v = sv[0]; int bi1 = 0;
        #pragma unroll
        for (int k = 1; k < 8; k++) if (sv[k] > b1v) { b1v = sv[k]; bi1 = k; }
        float b2v = -3.402823466e+38f; int bi2 = 0;
        #pragma unroll
        for (int k = 0; k < 8; k++) if (k != bi1 && sv[k] > b2v) { b2v = sv[k]; bi2 = k; }

        // Exchange expert results (lane 16+t) down to lane t: 3 shuffles.
        float x1v = __shfl_xor_sync(0xffffffffu, b1v, 16);
        float x2v = __shfl_xor_sync(0xffffffffu, b2v, 16);
        int   xid = __shfl_xor_sync(0xffffffffu, bi1 * 8 + bi2, 16);

        if (lane < T_TOK) {
            const int tok = tok0 + lane;
            const float g1v = b1v, g2v = b2v;
            const int   g1 = bi1, g2 = bi2;
            const float e1v = x1v, e2v = x2v;
            const int   e1 = xid >> 3, e2 = xid & 7;

            // combined scores in reference order: (g1,e1),(g1,e2),(g2,e1),(g2,e2)
            const float c0 = g1v + e1v;
            const float c1 = g1v + e2v;
            const float c2 = g2v + e1v;
            const float c3 = g2v + e2v;
            const float m  = fmaxf(fmaxf(c0, c1), fmaxf(c2, c3));
            float w0 = __expf(c0 - m);
            float w1 = __expf(c1 - m);
            float w2 = __expf(c2 - m);
            float w3 = __expf(c3 - m);
            const float inv = 1.0f / (w0 + w1 + w2 + w3);
            w0 *= inv; w1 *= inv; w2 *= inv; w3 *= inv;

            float4 idxv = make_float4((float)(g1 * 8 + e1), (float)(g1 * 8 + e2),
                                      (float)(g2 * 8 + e1), (float)(g2 * 8 + e2));
            float4 wv4  = make_float4(w0, w1, w2, w3);

            *reinterpret_cast<float4*>(out + (size_t)tok * 4) = idxv;
            *reinterpret_cast<float4*>(out + (size_t)TOKENS * 4 + (size_t)tok * 4) = wv4;
        }
    }
}

extern "C" void kernel_launch(void* const* d_in, const int* in_sizes, int n_in,
                              void* d_out, int out_size) {
    const float* x  = (const float*)d_in[0];
    const float* W1 = (const float*)d_in[1];
    const float* W2 = (const float*)d_in[2];
    float* out = (float*)d_out;

    cudaFuncSetAttribute(router_kernel,
                         cudaFuncAttributeMaxDynamicSharedMemorySize, SMEM_BYTES);
    router_kernel<<<GRID, BLOCK, SMEM_BYTES>>>(x, W1, W2, out);
}

// round 9
// speedup vs baseline: 1.1708x; 1.0089x over previous
#include <cuda_runtime.h>
#include <cstdint>

#define D_DIM   2048
#define NROWS   16
#define TOKENS  32768
#define T_TOK   4                    // tokens per warp-pair tile
#define NTILES  (TOKENS / T_TOK)     // 8192
#define BLOCK   512
#define GRID    152
#define NPAIRS_CTA (BLOCK / 64)      // 8 warp-pairs per CTA
#define SMEM_W   (NROWS * D_DIM * 4) // 131072 bytes for weights
#define XCH_FLOATS (NPAIRS_CTA * 2 * T_TOK * 4)  // pair x parity x tok x 4
#define SMEM_BYTES (SMEM_W + XCH_FLOATS * 4)

__device__ __forceinline__ void ffma2(unsigned long long &acc,
                                      unsigned long long a,
                                      unsigned long long b) {
    asm("fma.rn.f32x2 %0, %1, %2, %0;" : "+l"(acc) : "l"(a), "l"(b));
}

// Load one 128-float block (4 tokens, this lane's 4 floats each) into regs.
#define LOADX(buf, xq, blk)                                                    \
    {                                                                          \
        _Pragma("unroll")                                                      \
        for (int t = 0; t < T_TOK; t++)                                        \
            buf[t] = *reinterpret_cast<const ulonglong2*>(                     \
                (xq) + (size_t)t * D_DIM + (blk) * 128);                       \
    }

// FMA one block: this warp's 8 rows x 4 tokens.
#define COMPUTE8(buf, wq, blkoff)                                              \
    {                                                                          \
        _Pragma("unroll")                                                      \
        for (int r = 0; r < 8; r++) {                                          \
            ulonglong2 wv = *reinterpret_cast<const ulonglong2*>(              \
                (wq) + r * D_DIM + (blkoff));                                  \
            _Pragma("unroll")                                                  \
            for (int t = 0; t < T_TOK; t++) {                                  \
                ffma2(acc[r][t], buf[t].x, wv.x);                              \
                ffma2(acc[r][t], buf[t].y, wv.y);                              \
            }                                                                  \
        }                                                                      \
    }

extern "C" __global__ void __launch_bounds__(BLOCK, 1)
router_kernel(const float* __restrict__ x,
              const float* __restrict__ W1,
              const float* __restrict__ W2,
              float* __restrict__ out)
{
    extern __shared__ float Wsh[];           // rows 0..7 = W1, 8..15 = W2
    float* xch = Wsh + NROWS * D_DIM;        // pair exchange slots

    {
        int tid = threadIdx.x;
        for (int idx = tid * 4; idx < 8 * D_DIM; idx += BLOCK * 4) {
            *reinterpret_cast<float4*>(Wsh + idx) =
                *reinterpret_cast<const float4*>(W1 + idx);
            *reinterpret_cast<float4*>(Wsh + 8 * D_DIM + idx) =
                *reinterpret_cast<const float4*>(W2 + idx);
        }
        __syncthreads();
    }

    const int lane        = threadIdx.x & 31;
    const int wid         = threadIdx.x >> 5;
    const int pair_in_cta = wid >> 1;
    const int role        = wid & 1;          // 0 = group rows (W1), 1 = expert rows (W2)
    const int gpair       = blockIdx.x * NPAIRS_CTA + pair_in_cta;
    const int npairs      = GRID * NPAIRS_CTA;
    const int bar_id      = 8 + pair_in_cta;

    const float* wp = Wsh + role * 8 * D_DIM + lane * 4;

    int iterpar = 0;
    for (int tile = gpair; tile < NTILES; tile += npairs, iterpar ^= 1) {
        const int tok0 = tile * T_TOK;
        const float* xp = x + (size_t)tok0 * D_DIM + lane * 4;

        unsigned long long acc[8][T_TOK];
        #pragma unroll
        for (int r = 0; r < 8; r++)
            #pragma unroll
            for (int t = 0; t < T_TOK; t++)
                acc[r][t] = 0ull;

        // depth-2 x prefetch pipeline over 16 blocks of 128 floats
        ulonglong2 b0[T_TOK], b1[T_TOK];
        LOADX(b0, xp, 0);
        LOADX(b1, xp, 1);

        const float* wq = wp;
        const float* xq = xp;
        #pragma unroll 1
        for (int i = 0; i < 16; i += 2) {
            COMPUTE8(b0, wq, 0);
            if (i < 14) LOADX(b0, xq, 2);
            COMPUTE8(b1, wq, 128);
            if (i < 14) LOADX(b1, xq, 3);
            wq += 256;
            xq += 256;
        }

        // Split-lane reduction: row pairs (rp, rp+4). Lanes 0-15 finish row rp,
        // lanes 16-31 finish row rp+4. 6 shfl per (pair, token).
        float lo[4] = {0.f, 0.f, 0.f, 0.f};
        float hi[4] = {0.f, 0.f, 0.f, 0.f};
        #pragma unroll
        for (int rp = 0; rp < 4; rp++) {
            #pragma unroll
            for (int t = 0; t < T_TOK; t++) {
                float2 fa = *reinterpret_cast<float2*>(&acc[rp][t]);
                float2 fb = *reinterpret_cast<float2*>(&acc[rp + 4][t]);
                float a = fa.x + fa.y;
                float b = fb.x + fb.y;
                float ta = __shfl_xor_sync(0xffffffffu, a, 16);
                float tb = __shfl_xor_sync(0xffffffffu, b, 16);
                float v = (lane & 16) ? (b + tb) : (a + ta);
                v += __shfl_xor_sync(0xffffffffu, v, 8);
                v += __shfl_xor_sync(0xffffffffu, v, 4);
                v += __shfl_xor_sync(0xffffffffu, v, 2);
                v += __shfl_xor_sync(0xffffffffu, v, 1);
                if (lane == t)      lo[rp] = v;
                if (lane == 16 + t) hi[rp] = v;
            }
        }
        // Lane t gathers rows 4-7 from lane 16+t.
        float s[8];
        #pragma unroll
        for (int rp = 0; rp < 4; rp++) {
            s[rp]     = lo[rp];
            s[rp + 4] = __shfl_xor_sync(0xffffffffu, hi[rp], 16);
        }

        // top-2 of 8 (lax.top_k tie rule: lowest index wins). Valid on lanes 0-3.
        float v1 = s[0]; int i1 = 0;
        #pragma unroll
        for (int k = 1; k < 8; k++) if (s[k] > v1) { v1 = s[k]; i1 = k; }
        float v2 = -3.402823466e+38f; int i2 = 0;
        #pragma unroll
        for (int k = 0; k < 8; k++) if (k != i1 && s[k] > v2) { v2 = s[k]; i2 = k; }

        float* slot = xch + (((pair_in_cta << 1) | iterpar) * T_TOK + lane) * 4;

        if (role == 1 && lane < T_TOK) {      // expert warp publishes its top-2
            slot[0] = v1;
            slot[1] = v2;
            reinterpret_cast<int*>(slot)[2] = i1 * 8 + i2;
        }

        asm volatile("bar.sync %0, %1;" :: "r"(bar_id), "r"(64) : "memory");

        if (role == 0 && lane < T_TOK) {      // group warp finishes the token
            const int tok = tok0 + lane;
            const float g1v = v1, g2v = v2;
            const int   g1 = i1, g2 = i2;
            const float e1v = slot[0];
            const float e2v = slot[1];
            const int   eid = reinterpret_cast<int*>(slot)[2];
            const int   e1 = eid >> 3, e2 = eid & 7;

            const float c0 = g1v + e1v;
            const float c1 = g1v + e2v;
            const float c2 = g2v + e1v;
            const float c3 = g2v + e2v;
            const float m  = fmaxf(fmaxf(c0, c1), fmaxf(c2, c3));
            float w0 = __expf(c0 - m);
            float w1 = __expf(c1 - m);
            float w2 = __expf(c2 - m);
            float w3 = __expf(c3 - m);
            const float inv = 1.0f / (w0 + w1 + w2 + w3);
            w0 *= inv; w1 *= inv; w2 *= inv; w3 *= inv;

            float4 idxv = make_float4((float)(g1 * 8 + e1), (float)(g1 * 8 + e2),
                                      (float)(g2 * 8 + e1), (float)(g2 * 8 + e2));
            float4 wv4  = make_float4(w0, w1, w2, w3);

            *reinterpret_cast<float4*>(out + (size_t)tok * 4) = idxv;
            *reinterpret_cast<float4*>(out + (size_t)TOKENS * 4 + (size_t)tok * 4) = wv4;
        }
    }
}

extern "C" void kernel_launch(void* const* d_in, const int* in_sizes, int n_in,
                              void* d_out, int out_size) {
    const float* x  = (const float*)d_in[0];
    const float* W1 = (const float*)d_in[1];
    const float* W2 = (const float*)d_in[2];
    float* out = (float*)d_out;

    cudaFuncSetAttribute(router_kernel,
                         cudaFuncAttributeMaxDynamicSharedMemorySize, SMEM_BYTES);
    router_kernel<<<GRID, BLOCK, SMEM_BYTES>>>(x, W1, W2, out);
}